// round 5
// baseline (speedup 1.0000x reference)
#include <cuda_runtime.h>

typedef unsigned long long ull;

#define NB 2048
#define NT 200
#define NE 128
#define NH1 64
#define NH2 32
#define NEG_INF (-4294967295.0f)

#define SK_STRIDE 132   // floats per K row (padded)
#define SW_ROW    96    // floats per Weff row (8 chunks of 8 floats at stride 12)
#define SH_STRIDE 68    // floats per H1 row (padded)
#define SW2T_STRIDE 68  // floats per W2^T row (padded)

#define OFF_SK    0
#define OFF_SW    105600
#define OFF_SH    154752
#define OFF_SW2T  209152
#define OFF_SQ    217856
#define OFF_SQBP  218368
#define OFF_SQB   219392
#define OFF_SS    219648
#define OFF_SB2   220448
#define OFF_SW3   220576
#define OFF_SRED  220704
#define OFF_SPOOL 220768
#define SMEM_TOTAL 222832

__device__ __forceinline__ ull fma2(ull a, ull b, ull c) {
    ull d;
    asm("fma.rn.f32x2 %0, %1, %2, %3;" : "=l"(d) : "l"(a), "l"(b), "l"(c));
    return d;
}
__device__ __forceinline__ ull pack2(float x) {
    ull d; unsigned u = __float_as_uint(x);
    asm("mov.b64 %0, {%1, %1};" : "=l"(d) : "r"(u));
    return d;
}
__device__ __forceinline__ float2 unpack2(ull v) {
    float2 r;
    asm("mov.b64 {%0, %1}, %2;" : "=f"(r.x), "=f"(r.y) : "l"(v));
    return r;
}

__global__ __launch_bounds__(256, 1)
void attn_kernel(const float* __restrict__ queries, const float* __restrict__ keys,
                 const int* __restrict__ keys_id, const float* __restrict__ W1,
                 const float* __restrict__ b1, const float* __restrict__ W2,
                 const float* __restrict__ b2, const float* __restrict__ W3,
                 const float* __restrict__ b3, float* __restrict__ out)
{
    extern __shared__ char smem[];
    float* sK    = (float*)(smem + OFF_SK);
    float* sW    = (float*)(smem + OFF_SW);
    float* sH    = (float*)(smem + OFF_SH);
    float* sW2t  = (float*)(smem + OFF_SW2T);
    float* sQ    = (float*)(smem + OFF_SQ);
    float* sQBp  = (float*)(smem + OFF_SQBP);
    float* sQB   = (float*)(smem + OFF_SQB);
    float* sS    = (float*)(smem + OFF_SS);
    float* sB2   = (float*)(smem + OFF_SB2);
    float* sW3v  = (float*)(smem + OFF_SW3);
    float* sRed  = (float*)(smem + OFF_SRED);
    float* sPool = (float*)(smem + OFF_SPOOL);

    const int tid = threadIdx.x;
    const int b = blockIdx.x;

    // ---- Stage A: load q, K tile, W2^T, b2, W3 ----
    if (tid < NE) sQ[tid] = queries[b * NE + tid];
    {
        const float4* gK = (const float4*)(keys + (size_t)b * NT * NE);
        #pragma unroll 4
        for (int i = tid; i < NT * NE / 4; i += 256) {
            int t = i >> 5;       // 32 float4 per row
            int c = i & 31;
            *(float4*)(sK + t * SK_STRIDE + 4 * c) = gK[i];
        }
    }
    for (int i = tid; i < NH1 * NH2; i += 256) {
        int h = i >> 5, k = i & 31;
        sW2t[k * SW2T_STRIDE + h] = W2[i];
    }
    if (tid < NH2) { sB2[tid] = b2[tid]; sW3v[tid] = W3[tid]; }
    __syncthreads();

    // ---- Stage B: build Weff = (W1b - W1c) + q .* W1d ; qbias partials ----
    for (int i = tid; i < NE * NH1; i += 256) {
        int e = i >> 6, h = i & 63;
        float wb = W1[(NE + e) * NH1 + h];
        float wc = W1[(2 * NE + e) * NH1 + h];
        float wd = W1[(3 * NE + e) * NH1 + h];
        sW[e * SW_ROW + (h >> 3) * 12 + (h & 7)] = wb - wc + sQ[e] * wd;
    }
    {
        int h = tid & 63, seg = tid >> 6;
        float p = 0.f;
        int e0 = seg * 32;
        #pragma unroll 8
        for (int e = e0; e < e0 + 32; ++e)
            p += sQ[e] * (W1[e * NH1 + h] + W1[(2 * NE + e) * NH1 + h]);
        sQBp[seg * 64 + h] = p;
    }
    __syncthreads();
    if (tid < NH1)
        sQB[tid] = b1[tid] + sQBp[tid] + sQBp[64 + tid] + sQBp[128 + tid] + sQBp[192 + tid];
    __syncthreads();

    // ---- Stage D: h1 = relu(K @ Weff + qbias), 4t x 8h register tiles (f32x2) ----
    for (int task = tid; task < 400; task += 256) {
        int hb = task & 7;
        int tb = task >> 3;       // 0..49 ; rows tb, tb+50, tb+100, tb+150
        int h0 = hb * 8;
        ull acc[4][4];
        {
            const ull* qbp = (const ull*)(sQB + h0);
            ull q0 = qbp[0], q1 = qbp[1], q2 = qbp[2], q3 = qbp[3];
            #pragma unroll
            for (int i = 0; i < 4; ++i) { acc[i][0]=q0; acc[i][1]=q1; acc[i][2]=q2; acc[i][3]=q3; }
        }
        const float* kbase = sK + tb * SK_STRIDE;
        const float* wbase = sW + hb * 12;
        #pragma unroll 4
        for (int e = 0; e < NE; ++e) {
            ull kk0 = pack2(kbase[e]);
            ull kk1 = pack2(kbase[50  * SK_STRIDE + e]);
            ull kk2 = pack2(kbase[100 * SK_STRIDE + e]);
            ull kk3 = pack2(kbase[150 * SK_STRIDE + e]);
            const ulonglong2* wp = (const ulonglong2*)(wbase + e * SW_ROW);
            ulonglong2 wa = wp[0], wb = wp[1];
            acc[0][0] = fma2(kk0, wa.x, acc[0][0]);
            acc[0][1] = fma2(kk0, wa.y, acc[0][1]);
            acc[0][2] = fma2(kk0, wb.x, acc[0][2]);
            acc[0][3] = fma2(kk0, wb.y, acc[0][3]);
            acc[1][0] = fma2(kk1, wa.x, acc[1][0]);
            acc[1][1] = fma2(kk1, wa.y, acc[1][1]);
            acc[1][2] = fma2(kk1, wb.x, acc[1][2]);
            acc[1][3] = fma2(kk1, wb.y, acc[1][3]);
            acc[2][0] = fma2(kk2, wa.x, acc[2][0]);
            acc[2][1] = fma2(kk2, wa.y, acc[2][1]);
            acc[2][2] = fma2(kk2, wb.x, acc[2][2]);
            acc[2][3] = fma2(kk2, wb.y, acc[2][3]);
            acc[3][0] = fma2(kk3, wa.x, acc[3][0]);
            acc[3][1] = fma2(kk3, wa.y, acc[3][1]);
            acc[3][2] = fma2(kk3, wb.x, acc[3][2]);
            acc[3][3] = fma2(kk3, wb.y, acc[3][3]);
        }
        #pragma unroll
        for (int i = 0; i < 4; ++i) {
            float* dst = sH + (tb + 50 * i) * SH_STRIDE + h0;
            #pragma unroll
            for (int j = 0; j < 4; ++j) {
                float2 v = unpack2(acc[i][j]);
                dst[2 * j]     = fmaxf(v.x, 0.f);
                dst[2 * j + 1] = fmaxf(v.y, 0.f);
            }
        }
    }
    __syncthreads();

    // ---- Stage E: scores. warp = token stream, lane = H2 unit ----
    {
        int warp = tid >> 5, lane = tid & 31;
        float w3v = sW3v[lane];
        float b2v = sB2[lane];
        float b3v = b3[0];
        const ull* wrow = (const ull*)(sW2t + lane * SW2T_STRIDE);
        for (int t = warp; t < NT; t += 8) {
            const ull* hrow = (const ull*)(sH + t * SH_STRIDE);
            ull a2 = 0ull;  // (0.0f, 0.0f)
            #pragma unroll
            for (int j = 0; j < 32; ++j)
                a2 = fma2(hrow[j], wrow[j], a2);
            float2 v = unpack2(a2);
            float h2v = fmaxf(v.x + v.y + b2v, 0.f);
            float contrib = h2v * w3v;
            #pragma unroll
            for (int o = 16; o; o >>= 1)
                contrib += __shfl_xor_sync(0xffffffffu, contrib, o);
            if (lane == 0) {
                float sc = contrib + b3v;
                sS[t] = (keys_id[b * NT + t] != 0) ? sc : NEG_INF;
            }
        }
    }
    __syncthreads();

    // ---- Stage F: masked softmax over T ----
    {
        float v = (tid < NT) ? sS[tid] : -3.0e38f;
        float m = v;
        #pragma unroll
        for (int o = 16; o; o >>= 1) m = fmaxf(m, __shfl_xor_sync(0xffffffffu, m, o));
        if ((tid & 31) == 0) sRed[tid >> 5] = m;
        __syncthreads();
        float mx = sRed[0];
        #pragma unroll
        for (int i = 1; i < 8; ++i) mx = fmaxf(mx, sRed[i]);
        float p = (tid < NT) ? __expf(v - mx) : 0.f;
        float s = p;
        #pragma unroll
        for (int o = 16; o; o >>= 1) s += __shfl_xor_sync(0xffffffffu, s, o);
        __syncthreads();                  // sRed reuse barrier
        if ((tid & 31) == 0) sRed[tid >> 5] = s;
        __syncthreads();
        float tot = sRed[0] + sRed[1] + sRed[2] + sRed[3]
                  + sRed[4] + sRed[5] + sRed[6] + sRed[7];
        if (tid < NT) sS[tid] = p / tot;
    }
    __syncthreads();

    // ---- Stage G: out[e] = (1/T) * sum_t w[t] * K[t][e] ----
    {
        int pr = tid & 63;      // e-pair index
        int half = tid >> 6;    // 4 t-segments of 50
        ull a2 = 0ull;
        int t0 = half * 50;
        #pragma unroll 2
        for (int t = t0; t < t0 + 50; ++t) {
            ull wv = pack2(sS[t]);
            const ull* krow = (const ull*)(sK + t * SK_STRIDE);
            a2 = fma2(wv, krow[pr], a2);
        }
        float2 v = unpack2(a2);
        sPool[half * 128 + 2 * pr]     = v.x;
        sPool[half * 128 + 2 * pr + 1] = v.y;
    }
    __syncthreads();
    if (tid < NE) {
        float r = (sPool[tid] + sPool[128 + tid] + sPool[256 + tid] + sPool[384 + tid])
                  * (1.0f / NT);
        out[b * NE + tid] = r;
    }
}

extern "C" void kernel_launch(void* const* d_in, const int* in_sizes, int n_in,
                              void* d_out, int out_size) {
    const float* queries = (const float*)d_in[0];
    const float* keys    = (const float*)d_in[1];
    const int*   keys_id = (const int*)  d_in[2];
    const float* W1      = (const float*)d_in[3];
    const float* b1      = (const float*)d_in[4];
    const float* W2      = (const float*)d_in[5];
    const float* b2      = (const float*)d_in[6];
    const float* W3      = (const float*)d_in[7];
    const float* b3      = (const float*)d_in[8];
    float* out = (float*)d_out;

    cudaFuncSetAttribute(attn_kernel,
                         cudaFuncAttributeMaxDynamicSharedMemorySize, SMEM_TOTAL);
    attn_kernel<<<NB, 256, SMEM_TOTAL>>>(queries, keys, keys_id,
                                         W1, b1, W2, b2, W3, b3, out);
}

// round 6
// speedup vs baseline: 1.2165x; 1.2165x over previous
#include <cuda_runtime.h>
#include <cstdint>

typedef unsigned long long ull;

#define NB 2048
#define NT 200
#define NE 128
#define NH1 64
#define NH2 32
#define NEG_INF (-4294967295.0f)

#define SK_STRIDE 132    // floats per K row (padded)
#define SWP_ROW   96     // ull per Weff e-pair row: 16 chunks of 4 ull at stride 6
#define SH_STRIDE 68     // floats per H1 row (padded)
#define SW2T_STRIDE 70   // floats per W2^T row (padded, conflict-free LDS.64)

#define OFF_SK    0        // 105600 B
#define OFF_SWP   105600   // 49152 B
#define OFF_SH    154752   // 54400 B
#define OFF_SW2T  209152   // 8960 B
#define OFF_SQ    218112   // 512 B
#define OFF_SQBP  218624   // 2048 B
#define OFF_SQB   220672   // 256 B
#define OFF_SS    220928   // 800 B
#define OFF_SB2   221728   // 128 B
#define OFF_SW3   221856   // 128 B
#define OFF_SRED  221984   // 64 B
#define OFF_SPOOL 222048   // 4096 B
#define SMEM_TOTAL 226144

__device__ __forceinline__ ull fma2(ull a, ull b, ull c) {
    ull d;
    asm("fma.rn.f32x2 %0, %1, %2, %3;" : "=l"(d) : "l"(a), "l"(b), "l"(c));
    return d;
}
__device__ __forceinline__ ull pack2(float x) {
    ull d; unsigned u = __float_as_uint(x);
    asm("mov.b64 %0, {%1, %1};" : "=l"(d) : "r"(u));
    return d;
}
__device__ __forceinline__ float2 unpack2(ull v) {
    float2 r;
    asm("mov.b64 {%0, %1}, %2;" : "=f"(r.x), "=f"(r.y) : "l"(v));
    return r;
}
__device__ __forceinline__ void cp_async16(void* smem_dst, const void* gmem_src) {
    uint32_t s = (uint32_t)__cvta_generic_to_shared(smem_dst);
    asm volatile("cp.async.cg.shared.global [%0], [%1], 16;" :: "r"(s), "l"(gmem_src));
}

__global__ __launch_bounds__(512, 1)
void attn_kernel(const float* __restrict__ queries, const float* __restrict__ keys,
                 const int* __restrict__ keys_id, const float* __restrict__ W1,
                 const float* __restrict__ b1, const float* __restrict__ W2,
                 const float* __restrict__ b2, const float* __restrict__ W3,
                 const float* __restrict__ b3, float* __restrict__ out)
{
    extern __shared__ char smem[];
    float* sK    = (float*)(smem + OFF_SK);
    ull*   sWp   = (ull*)  (smem + OFF_SWP);
    float* sH    = (float*)(smem + OFF_SH);
    float* sW2t  = (float*)(smem + OFF_SW2T);
    float* sQ    = (float*)(smem + OFF_SQ);
    float* sQBp  = (float*)(smem + OFF_SQBP);
    float* sQB   = (float*)(smem + OFF_SQB);
    float* sS    = (float*)(smem + OFF_SS);
    float* sB2   = (float*)(smem + OFF_SB2);
    float* sW3v  = (float*)(smem + OFF_SW3);
    float* sRed  = (float*)(smem + OFF_SRED);
    float* sPool = (float*)(smem + OFF_SPOOL);

    const int tid = threadIdx.x;
    const int b = blockIdx.x;

    // ---- Stage A: async K tile load (overlapped with Weff build) ----
    {
        const float4* gK = (const float4*)(keys + (size_t)b * NT * NE);
        #pragma unroll 4
        for (int i = tid; i < NT * NE / 4; i += 512) {
            int t = i >> 5;        // 32 float4 per row
            int c = i & 31;
            cp_async16(sK + t * SK_STRIDE + 4 * c, gK + i);
        }
        asm volatile("cp.async.commit_group;");
    }
    if (tid < NE) sQ[tid] = queries[b * NE + tid];
    for (int i = tid; i < NH1 * NH2; i += 512) {
        int h = i >> 5, k = i & 31;
        sW2t[k * SW2T_STRIDE + h] = W2[i];
    }
    if (tid < NH2) { sB2[tid] = b2[tid]; sW3v[tid] = W3[tid]; }
    __syncthreads();   // sQ visible for stage B

    // ---- Stage B: Weff = (W1b - W1c) + q .* W1d, e-pair interleaved; qbias ----
    for (int i = tid; i < NE * NH1; i += 512) {
        int e = i >> 6, h = i & 63;
        float wb = W1[(NE + e) * NH1 + h];
        float wc = W1[(2 * NE + e) * NH1 + h];
        float wd = W1[(3 * NE + e) * NH1 + h];
        // layout: ull index = (e/2)*96 + (h/4)*6 + (h&3); lane = e&1
        float* dst = (float*)(sWp + (e >> 1) * SWP_ROW + (h >> 2) * 6 + (h & 3));
        dst[e & 1] = wb - wc + sQ[e] * wd;
    }
    {
        int h = tid & 63, seg = tid >> 6;   // 8 segments of 16 e
        float p = 0.f;
        int e0 = seg * 16;
        #pragma unroll 4
        for (int e = e0; e < e0 + 16; ++e)
            p += sQ[e] * (W1[e * NH1 + h] + W1[(2 * NE + e) * NH1 + h]);
        sQBp[seg * 64 + h] = p;
    }
    asm volatile("cp.async.wait_group 0;");
    __syncthreads();   // sK, sWp, sQBp visible

    if (tid < NH1) {
        float s = b1[tid];
        #pragma unroll
        for (int i = 0; i < 8; ++i) s += sQBp[i * 64 + tid];
        sQB[tid] = s;
    }
    __syncthreads();

    // ---- Stage D: h1 = relu(K @ Weff + qbias). 4t x 4h tiles, e-pair f32x2 ----
    for (int task = tid; task < 800; task += 512) {
        int hb = task & 15;       // 16 h-blocks of 4
        int tb = task >> 4;       // 0..49 ; rows tb, tb+50, tb+100, tb+150
        int h0 = hb * 4;
        ull acc[4][4];
        #pragma unroll
        for (int i = 0; i < 4; ++i)
            #pragma unroll
            for (int j = 0; j < 4; ++j) acc[i][j] = 0ull;

        const ull* k0 = (const ull*)sK + tb * (SK_STRIDE / 2);  // 66 ull/row
        const ull* wbase = sWp + hb * 6;
        #pragma unroll 4
        for (int ep = 0; ep < NE / 2; ++ep) {
            ull kk0 = k0[ep];
            ull kk1 = k0[50  * (SK_STRIDE / 2) + ep];
            ull kk2 = k0[100 * (SK_STRIDE / 2) + ep];
            ull kk3 = k0[150 * (SK_STRIDE / 2) + ep];
            const ulonglong2* wp = (const ulonglong2*)(wbase + ep * SWP_ROW);
            ulonglong2 wa = wp[0], wb = wp[1];  // h0, h0+1, h0+2, h0+3
            acc[0][0] = fma2(kk0, wa.x, acc[0][0]);
            acc[0][1] = fma2(kk0, wa.y, acc[0][1]);
            acc[0][2] = fma2(kk0, wb.x, acc[0][2]);
            acc[0][3] = fma2(kk0, wb.y, acc[0][3]);
            acc[1][0] = fma2(kk1, wa.x, acc[1][0]);
            acc[1][1] = fma2(kk1, wa.y, acc[1][1]);
            acc[1][2] = fma2(kk1, wb.x, acc[1][2]);
            acc[1][3] = fma2(kk1, wb.y, acc[1][3]);
            acc[2][0] = fma2(kk2, wa.x, acc[2][0]);
            acc[2][1] = fma2(kk2, wa.y, acc[2][1]);
            acc[2][2] = fma2(kk2, wb.x, acc[2][2]);
            acc[2][3] = fma2(kk2, wb.y, acc[2][3]);
            acc[3][0] = fma2(kk3, wa.x, acc[3][0]);
            acc[3][1] = fma2(kk3, wa.y, acc[3][1]);
            acc[3][2] = fma2(kk3, wb.x, acc[3][2]);
            acc[3][3] = fma2(kk3, wb.y, acc[3][3]);
        }
        float qb0 = sQB[h0], qb1 = sQB[h0 + 1], qb2 = sQB[h0 + 2], qb3 = sQB[h0 + 3];
        #pragma unroll
        for (int i = 0; i < 4; ++i) {
            float* dst = sH + (tb + 50 * i) * SH_STRIDE + h0;
            float2 v0 = unpack2(acc[i][0]);
            float2 v1 = unpack2(acc[i][1]);
            float2 v2 = unpack2(acc[i][2]);
            float2 v3 = unpack2(acc[i][3]);
            dst[0] = fmaxf(v0.x + v0.y + qb0, 0.f);
            dst[1] = fmaxf(v1.x + v1.y + qb1, 0.f);
            dst[2] = fmaxf(v2.x + v2.y + qb2, 0.f);
            dst[3] = fmaxf(v3.x + v3.y + qb3, 0.f);
        }
    }
    __syncthreads();

    // ---- Stage E: scores. warp = token stream, lane = H2 unit ----
    {
        int warp = tid >> 5, lane = tid & 31;
        float w3v = sW3v[lane];
        float b2v = sB2[lane];
        float b3v = b3[0];
        const ull* wrow = (const ull*)(sW2t + lane * SW2T_STRIDE);
        for (int t = warp; t < NT; t += 16) {
            const ull* hrow = (const ull*)(sH + t * SH_STRIDE);
            ull a2 = 0ull;
            #pragma unroll
            for (int j = 0; j < 32; ++j)
                a2 = fma2(hrow[j], wrow[j], a2);
            float2 v = unpack2(a2);
            float h2v = fmaxf(v.x + v.y + b2v, 0.f);
            float contrib = h2v * w3v;
            #pragma unroll
            for (int o = 16; o; o >>= 1)
                contrib += __shfl_xor_sync(0xffffffffu, contrib, o);
            if (lane == 0) {
                float sc = contrib + b3v;
                sS[t] = (keys_id[b * NT + t] != 0) ? sc : NEG_INF;
            }
        }
    }
    __syncthreads();

    // ---- Stage F: masked softmax over T ----
    {
        float v = (tid < NT) ? sS[tid] : -3.0e38f;
        float m = v;
        #pragma unroll
        for (int o = 16; o; o >>= 1) m = fmaxf(m, __shfl_xor_sync(0xffffffffu, m, o));
        if ((tid & 31) == 0) sRed[tid >> 5] = m;
        __syncthreads();
        float mx = sRed[0];
        #pragma unroll
        for (int i = 1; i < 16; ++i) mx = fmaxf(mx, sRed[i]);
        float p = (tid < NT) ? __expf(v - mx) : 0.f;
        float s = p;
        #pragma unroll
        for (int o = 16; o; o >>= 1) s += __shfl_xor_sync(0xffffffffu, s, o);
        __syncthreads();                  // sRed reuse barrier
        if ((tid & 31) == 0) sRed[tid >> 5] = s;
        __syncthreads();
        float tot = 0.f;
        #pragma unroll
        for (int i = 0; i < 16; ++i) tot += sRed[i];
        if (tid < NT) sS[tid] = p / tot;
    }
    __syncthreads();

    // ---- Stage G: out[e] = (1/T) * sum_t w[t] * K[t][e] ----
    {
        int pr = tid & 63;      // e-pair index
        int seg = tid >> 6;     // 8 t-segments of 25
        ull a2 = 0ull;
        int t0 = seg * 25;
        #pragma unroll 5
        for (int t = t0; t < t0 + 25; ++t) {
            ull wv = pack2(sS[t]);
            const ull* krow = (const ull*)(sK + t * SK_STRIDE);
            a2 = fma2(wv, krow[pr], a2);
        }
        float2 v = unpack2(a2);
        sPool[seg * 128 + 2 * pr]     = v.x;
        sPool[seg * 128 + 2 * pr + 1] = v.y;
    }
    __syncthreads();
    if (tid < NE) {
        float r = 0.f;
        #pragma unroll
        for (int i = 0; i < 8; ++i) r += sPool[i * 128 + tid];
        out[b * NE + tid] = r * (1.0f / NT);
    }
}

extern "C" void kernel_launch(void* const* d_in, const int* in_sizes, int n_in,
                              void* d_out, int out_size) {
    const float* queries = (const float*)d_in[0];
    const float* keys    = (const float*)d_in[1];
    const int*   keys_id = (const int*)  d_in[2];
    const float* W1      = (const float*)d_in[3];
    const float* b1      = (const float*)d_in[4];
    const float* W2      = (const float*)d_in[5];
    const float* b2      = (const float*)d_in[6];
    const float* W3      = (const float*)d_in[7];
    const float* b3      = (const float*)d_in[8];
    float* out = (float*)d_out;

    cudaFuncSetAttribute(attn_kernel,
                         cudaFuncAttributeMaxDynamicSharedMemorySize, SMEM_TOTAL);
    attn_kernel<<<NB, 512, SMEM_TOTAL>>>(queries, keys, keys_id,
                                         W1, b1, W2, b2, W3, b3, out);
}